// round 3
// baseline (speedup 1.0000x reference)
#include <cuda_runtime.h>
#include <cstdint>

// ---------------- scratch (no allocations allowed) ----------------
// qkv:  [8][768][4096]  fp32   (100.7 MB)
// agg:  [8][768][4096]  fp32   (100.7 MB)
// att:  [8][512][4096]  fp32   ( 67.1 MB)
// kv :  [8][64][72]     fp32
__device__ float g_qkv[(size_t)8 * 768 * 4096];
__device__ float g_agg[(size_t)8 * 768 * 4096];
__device__ float g_att[(size_t)8 * 512 * 4096];
__device__ float g_kv[8 * 64 * 72];

#define HW 4096
#define NB 8

// ---------------- SGEMM: C[b] = A(MxK) * B[b](K x 4096), optional BN epilogue ----------------
// BM=128 BN=128 BK=16, 256 threads, 8x8 microtile.
#define BM 128
#define BNT 128
#define BK 16
#define BMP 132  // padded leading dim for As

__global__ __launch_bounds__(256, 2)
void sgemm_kernel(const float* __restrict__ A,     // [M,K] row-major
                  const float* __restrict__ Bsrc,  // [NB][K][4096]
                  float* __restrict__ Cdst,        // [NB][M][4096]
                  int M, int K,
                  const float* __restrict__ bn_gamma,
                  const float* __restrict__ bn_beta,
                  const float* __restrict__ bn_mean,
                  const float* __restrict__ bn_var)
{
    const int b  = blockIdx.z;
    const float* Bp = Bsrc + (size_t)b * K * HW;
    float* Cp       = Cdst + (size_t)b * M * HW;
    const int bm = blockIdx.y * BM;
    const int bn = blockIdx.x * BNT;

    __shared__ float As[BK][BMP];
    __shared__ float Bs[BK][BNT];

    const int tid = threadIdx.x;
    const int tx = tid & 15;   // 0..15 -> N
    const int ty = tid >> 4;   // 0..15 -> M

    float acc[8][8];
#pragma unroll
    for (int i = 0; i < 8; i++)
#pragma unroll
        for (int j = 0; j < 8; j++) acc[i][j] = 0.f;

    for (int k0 = 0; k0 < K; k0 += BK) {
        // A tile: 128 rows x 16 cols, scalar coalesced (16 lanes per row), transposed store
#pragma unroll
        for (int i = 0; i < (BM * BK) / 256; ++i) {  // 8
            int idx = tid + i * 256;
            int k = idx & 15, m = idx >> 4;
            As[k][m] = A[(size_t)(bm + m) * K + k0 + k];
        }
        // B tile: 16 rows x 128 cols, float4
#pragma unroll
        for (int i = 0; i < 2; ++i) {
            int idx = tid + i * 256;   // 0..511 float4 slots
            int k  = idx >> 5;         // 32 float4 per row
            int n4 = idx & 31;
            float4 v = *reinterpret_cast<const float4*>(
                &Bp[(size_t)(k0 + k) * HW + bn + n4 * 4]);
            *reinterpret_cast<float4*>(&Bs[k][n4 * 4]) = v;
        }
        __syncthreads();

#pragma unroll
        for (int kk = 0; kk < BK; ++kk) {
            float af[8], bf[8];
#pragma unroll
            for (int i = 0; i < 8; i++) af[i] = As[kk][ty * 8 + i];
#pragma unroll
            for (int j = 0; j < 8; j++) bf[j] = Bs[kk][tx * 8 + j];
#pragma unroll
            for (int i = 0; i < 8; i++)
#pragma unroll
                for (int j = 0; j < 8; j++)
                    acc[i][j] = fmaf(af[i], bf[j], acc[i][j]);
        }
        __syncthreads();
    }

#pragma unroll
    for (int i = 0; i < 8; i++) {
        int m = bm + ty * 8 + i;
        float s = 1.f, bb = 0.f;
        if (bn_gamma) {
            float inv = bn_gamma[m] * rsqrtf(bn_var[m] + 1e-5f);
            s = inv;
            bb = bn_beta[m] - bn_mean[m] * inv;
        }
        float* crow = Cp + (size_t)m * HW + bn + tx * 8;
#pragma unroll
        for (int j = 0; j < 8; j += 4) {
            float4 v;
            v.x = acc[i][j + 0] * s + bb;
            v.y = acc[i][j + 1] * s + bb;
            v.z = acc[i][j + 2] * s + bb;
            v.w = acc[i][j + 3] * s + bb;
            *reinterpret_cast<float4*>(crow + j) = v;
        }
    }
}

// ---------------- fused depthwise 5x5 + grouped pointwise 8x8 -> agg ----------------
// grid: (4 spatial tiles of 32x32, 96 groups, 8 batch), 256 threads
__global__ __launch_bounds__(256, 2)
void dwpw_kernel(const float* __restrict__ qkv,
                 const float* __restrict__ w_dw,  // [768][25]
                 const float* __restrict__ w_pw,  // [96][8][8]
                 float* __restrict__ agg)
{
    const int tile = blockIdx.x;
    const int g = blockIdx.y;
    const int b = blockIdx.z;
    const int ty0 = (tile >> 1) * 32;
    const int tx0 = (tile & 1) * 32;

    __shared__ float s_in[8][36][36];  // 41472 B
    __shared__ float s_dw[8][25];
    __shared__ float s_pw[8][8];

    const int tid = threadIdx.x;
    if (tid < 200) s_dw[tid / 25][tid % 25] = w_dw[(g * 8 + tid / 25) * 25 + tid % 25];
    if (tid < 64)  s_pw[tid >> 3][tid & 7] = w_pw[g * 64 + tid];

    const float* base = qkv + ((size_t)b * 768 + g * 8) * HW;
    for (int idx = tid; idx < 8 * 36 * 36; idx += 256) {
        int c = idx / 1296;
        int rem = idx - c * 1296;
        int r = rem / 36;
        int col = rem - r * 36;
        int y = ty0 + r - 2, x = tx0 + col - 2;
        float v = 0.f;
        if (y >= 0 && y < 64 && x >= 0 && x < 64) v = base[(size_t)c * HW + y * 64 + x];
        s_in[c][r][col] = v;
    }
    __syncthreads();

    float* obase = agg + ((size_t)b * 768 + g * 8) * HW;
#pragma unroll
    for (int pi = 0; pi < 4; ++pi) {
        int p = tid + pi * 256;     // within 32x32 tile
        int py = p >> 5, px = p & 31;
        float dwv[8];
#pragma unroll
        for (int c = 0; c < 8; ++c) {
            float a = 0.f;
#pragma unroll
            for (int dy = 0; dy < 5; ++dy)
#pragma unroll
                for (int dx = 0; dx < 5; ++dx)
                    a = fmaf(s_in[c][py + dy][px + dx], s_dw[c][dy * 5 + dx], a);
            dwv[c] = a;
        }
        int off = (ty0 + py) * 64 + (tx0 + px);
#pragma unroll
        for (int o = 0; o < 8; ++o) {
            float a = 0.f;
#pragma unroll
            for (int c = 0; c < 8; ++c) a = fmaf(s_pw[o][c], dwv[c], a);
            obase[(size_t)o * HW + off] = a;
        }
    }
}

// ---------------- kv = sum_p relu(k)_d * [v_e | 1]  per (b, head) ----------------
// grid (64 heads, 8 batch), 256 threads
__global__ __launch_bounds__(256, 4)
void kv_kernel(const float* __restrict__ qkv,
               const float* __restrict__ agg,
               float* __restrict__ kvout)
{
    const int h = blockIdx.x, b = blockIdx.y;
    const float* src = (h < 32) ? qkv : agg;
    const int cbase = (h & 31) * 24;
    const float* kp = src + ((size_t)b * 768 + cbase + 8) * HW;
    const float* vp = src + ((size_t)b * 768 + cbase + 16) * HW;

    float acc[8][9];
#pragma unroll
    for (int d = 0; d < 8; d++)
#pragma unroll
        for (int e = 0; e < 9; e++) acc[d][e] = 0.f;

    for (int p = threadIdx.x; p < HW; p += 256) {
        float kk[8], vv[8];
#pragma unroll
        for (int d = 0; d < 8; d++) kk[d] = fmaxf(kp[(size_t)d * HW + p], 0.f);
#pragma unroll
        for (int e = 0; e < 8; e++) vv[e] = vp[(size_t)e * HW + p];
#pragma unroll
        for (int d = 0; d < 8; d++) {
#pragma unroll
            for (int e = 0; e < 8; e++) acc[d][e] = fmaf(kk[d], vv[e], acc[d][e]);
            acc[d][8] += kk[d];
        }
    }

    __shared__ float red[8][72];
    const int lane = threadIdx.x & 31, w = threadIdx.x >> 5;
#pragma unroll
    for (int i = 0; i < 72; ++i) {
        float v = acc[i / 9][i % 9];
#pragma unroll
        for (int off = 16; off; off >>= 1) v += __shfl_down_sync(0xffffffffu, v, off);
        if (lane == 0) red[w][i] = v;
    }
    __syncthreads();
    if (threadIdx.x < 72) {
        float s = 0.f;
#pragma unroll
        for (int w2 = 0; w2 < 8; ++w2) s += red[w2][threadIdx.x];
        kvout[((size_t)b * 64 + h) * 72 + threadIdx.x] = s;
    }
}

// ---------------- out = (relu(q) @ kv)[:8] / ((relu(q) @ kv)[8] + eps) ----------------
// grid (16 pixel tiles, 64 heads, 8 batch), 256 threads, 1 pixel/thread
__global__ __launch_bounds__(256, 4)
void apply_kernel(const float* __restrict__ qkv,
                  const float* __restrict__ agg,
                  const float* __restrict__ kvin,
                  float* __restrict__ att)
{
    const int h = blockIdx.y, b = blockIdx.z;
    __shared__ float kv[8][9];
    if (threadIdx.x < 72)
        kv[threadIdx.x / 9][threadIdx.x % 9] = kvin[((size_t)b * 64 + h) * 72 + threadIdx.x];
    __syncthreads();

    const float* src = (h < 32) ? qkv : agg;
    const int cbase = (h & 31) * 24;
    const float* qp = src + ((size_t)b * 768 + cbase) * HW;
    const int p = blockIdx.x * 256 + threadIdx.x;

    float q[8];
#pragma unroll
    for (int d = 0; d < 8; d++) q[d] = fmaxf(qp[(size_t)d * HW + p], 0.f);

    float den = 0.f;
#pragma unroll
    for (int d = 0; d < 8; d++) den = fmaf(q[d], kv[d][8], den);
    const float inv = 1.f / (den + 1e-15f);

    float* op = att + ((size_t)b * 512 + h * 8) * HW + p;
#pragma unroll
    for (int n = 0; n < 8; ++n) {
        float s = 0.f;
#pragma unroll
        for (int d = 0; d < 8; d++) s = fmaf(q[d], kv[d][n], s);
        op[(size_t)n * HW] = s * inv;
    }
}

// ---------------- launch ----------------
extern "C" void kernel_launch(void* const* d_in, const int* in_sizes, int n_in,
                              void* d_out, int out_size)
{
    const float* x        = (const float*)d_in[0];  // [8][256][4096]
    const float* w_qkv    = (const float*)d_in[1];  // [768][256]
    const float* w_dw     = (const float*)d_in[2];  // [768][1][5][5]
    const float* w_pw     = (const float*)d_in[3];  // [96][8][8]
    const float* w_proj   = (const float*)d_in[4];  // [256][512]
    const float* bn_gamma = (const float*)d_in[5];
    const float* bn_beta  = (const float*)d_in[6];
    const float* bn_mean  = (const float*)d_in[7];
    const float* bn_var   = (const float*)d_in[8];
    float* out = (float*)d_out;                     // [8][256][4096]

    float *qkv, *agg, *att, *kv;
    cudaGetSymbolAddress((void**)&qkv, g_qkv);
    cudaGetSymbolAddress((void**)&agg, g_agg);
    cudaGetSymbolAddress((void**)&att, g_att);
    cudaGetSymbolAddress((void**)&kv,  g_kv);

    // 1) qkv = w_qkv @ x         (M=768, K=256)
    sgemm_kernel<<<dim3(HW / BNT, 768 / BM, NB), 256>>>(
        w_qkv, x, qkv, 768, 256, nullptr, nullptr, nullptr, nullptr);

    // 2) agg = grouped-pw(depthwise5x5(qkv))
    dwpw_kernel<<<dim3(4, 96, NB), 256>>>(qkv, w_dw, w_pw, agg);

    // 3) kv reduction per (b, head)
    kv_kernel<<<dim3(64, NB), 256>>>(qkv, agg, kv);

    // 4) normalize / apply -> att [8][512][4096]
    apply_kernel<<<dim3(HW / 256, 64, NB), 256>>>(qkv, agg, kv, att);

    // 5) out = BN(w_proj @ att)  (M=256, K=512)
    sgemm_kernel<<<dim3(HW / BNT, 256 / BM, NB), 256>>>(
        w_proj, att, out, 256, 512, bn_gamma, bn_beta, bn_mean, bn_var);
}

// round 7
// speedup vs baseline: 1.0787x; 1.0787x over previous
#include <cuda_runtime.h>
#include <cstdint>

// ---------------- scratch (no allocations allowed) ----------------
__device__ float g_qkv[(size_t)8 * 768 * 4096];
__device__ float g_agg[(size_t)8 * 768 * 4096];
__device__ float g_att[(size_t)8 * 512 * 4096];
__device__ float g_kv[8 * 64 * 72];

#define HW 4096
#define NB 8

__device__ __forceinline__ uint32_t f2tf32(float x) {
    uint32_t u;
    asm("cvt.rna.tf32.f32 %0, %1;" : "=r"(u) : "f"(x));
    return u;
}

#define MMA_TF32(C, Ar, Br)                                              \
    asm volatile(                                                        \
        "mma.sync.aligned.m16n8k8.row.col.f32.tf32.tf32.f32 "            \
        "{%0,%1,%2,%3}, {%4,%5,%6,%7}, {%8,%9}, {%0,%1,%2,%3};"          \
        : "+f"((C)[0]), "+f"((C)[1]), "+f"((C)[2]), "+f"((C)[3])         \
        : "r"((Ar)[0]), "r"((Ar)[1]), "r"((Ar)[2]), "r"((Ar)[3]),        \
          "r"((Br)[0]), "r"((Br)[1]))

// ---------------- 3xTF32 tensor-core GEMM (fp32 accuracy) ----------------
// C[b](M x 4096) = A(M x K) * B[b](K x 4096), optional fused BN epilogue.
// Block tile 128x128x16, 256 threads = 8 warps (2M x 4N), warp tile 64x32.
// Each operand split big/small tf32; per tile: bb + bs + sb mma.
__global__ __launch_bounds__(256)
void mma_gemm_kernel(const float* __restrict__ A,     // [M,K] row-major
                     const float* __restrict__ Bsrc,  // [NB][K][4096]
                     float* __restrict__ Cdst,        // [NB][M][4096]
                     int M, int K,
                     const float* __restrict__ bn_gamma,
                     const float* __restrict__ bn_beta,
                     const float* __restrict__ bn_mean,
                     const float* __restrict__ bn_var)
{
    const int b  = blockIdx.z;
    const float* Bp = Bsrc + (size_t)b * K * HW;
    float* Cp       = Cdst + (size_t)b * M * HW;
    const int bm = blockIdx.y * 128;
    const int bn = blockIdx.x * 128;

    __shared__ uint32_t As_b[128][20];   // [m][k] big, pad 20
    __shared__ uint32_t As_s[128][20];   // small
    __shared__ uint32_t Bs_b[16][136];   // [k][n] big, pad 136
    __shared__ uint32_t Bs_s[16][136];

    const int tid  = threadIdx.x;
    const int lane = tid & 31;
    const int warp = tid >> 5;
    const int warpM = (warp >> 2) * 64;   // 0 or 64
    const int warpN = (warp & 3) * 32;    // 0,32,64,96
    const int lq = lane >> 2;             // 0..7
    const int lr = lane & 3;              // 0..3

    float c[4][4][4];
#pragma unroll
    for (int mi = 0; mi < 4; mi++)
#pragma unroll
        for (int ni = 0; ni < 4; ni++)
#pragma unroll
            for (int r = 0; r < 4; r++) c[mi][ni][r] = 0.f;

    for (int k0 = 0; k0 < K; k0 += 16) {
        // ---- A tile: 128 rows x 16 k (512 float4) ----
#pragma unroll
        for (int i = 0; i < 2; ++i) {
            int fidx = tid + i * 256;
            int row  = fidx >> 2;
            int k4   = (fidx & 3) * 4;
            float4 v = *reinterpret_cast<const float4*>(
                &A[(size_t)(bm + row) * K + k0 + k4]);
            uint32_t bx = f2tf32(v.x), by = f2tf32(v.y),
                     bz = f2tf32(v.z), bw = f2tf32(v.w);
            As_b[row][k4 + 0] = bx;
            As_b[row][k4 + 1] = by;
            As_b[row][k4 + 2] = bz;
            As_b[row][k4 + 3] = bw;
            As_s[row][k4 + 0] = f2tf32(v.x - __uint_as_float(bx));
            As_s[row][k4 + 1] = f2tf32(v.y - __uint_as_float(by));
            As_s[row][k4 + 2] = f2tf32(v.z - __uint_as_float(bz));
            As_s[row][k4 + 3] = f2tf32(v.w - __uint_as_float(bw));
        }
        // ---- B tile: 16 k x 128 n (512 float4) ----
#pragma unroll
        for (int i = 0; i < 2; ++i) {
            int fidx = tid + i * 256;
            int k    = fidx >> 5;
            int n4   = (fidx & 31) * 4;
            float4 v = *reinterpret_cast<const float4*>(
                &Bp[(size_t)(k0 + k) * HW + bn + n4]);
            uint32_t bx = f2tf32(v.x), by = f2tf32(v.y),
                     bz = f2tf32(v.z), bw = f2tf32(v.w);
            Bs_b[k][n4 + 0] = bx;
            Bs_b[k][n4 + 1] = by;
            Bs_b[k][n4 + 2] = bz;
            Bs_b[k][n4 + 3] = bw;
            Bs_s[k][n4 + 0] = f2tf32(v.x - __uint_as_float(bx));
            Bs_s[k][n4 + 1] = f2tf32(v.y - __uint_as_float(by));
            Bs_s[k][n4 + 2] = f2tf32(v.z - __uint_as_float(bz));
            Bs_s[k][n4 + 3] = f2tf32(v.w - __uint_as_float(bw));
        }
        __syncthreads();

#pragma unroll
        for (int ks = 0; ks < 2; ++ks) {
            const int kb = ks * 8;
            uint32_t ab[4][4], as[4][4], bb[4][2], bs[4][2];
#pragma unroll
            for (int mi = 0; mi < 4; ++mi) {
                int r  = warpM + mi * 16 + lq;
                int kc = kb + lr;
                ab[mi][0] = As_b[r][kc];
                ab[mi][1] = As_b[r + 8][kc];
                ab[mi][2] = As_b[r][kc + 4];
                ab[mi][3] = As_b[r + 8][kc + 4];
                as[mi][0] = As_s[r][kc];
                as[mi][1] = As_s[r + 8][kc];
                as[mi][2] = As_s[r][kc + 4];
                as[mi][3] = As_s[r + 8][kc + 4];
            }
#pragma unroll
            for (int ni = 0; ni < 4; ++ni) {
                int col = warpN + ni * 8 + lq;
                int kr  = kb + lr;
                bb[ni][0] = Bs_b[kr][col];
                bb[ni][1] = Bs_b[kr + 4][col];
                bs[ni][0] = Bs_s[kr][col];
                bs[ni][1] = Bs_s[kr + 4][col];
            }
#pragma unroll
            for (int mi = 0; mi < 4; ++mi)
#pragma unroll
                for (int ni = 0; ni < 4; ++ni) {
                    MMA_TF32(c[mi][ni], as[mi], bb[ni]);  // small x big
                    MMA_TF32(c[mi][ni], ab[mi], bs[ni]);  // big x small
                    MMA_TF32(c[mi][ni], ab[mi], bb[ni]);  // big x big
                }
        }
        __syncthreads();
    }

    // ---- epilogue: optional BN, float2 stores ----
#pragma unroll
    for (int mi = 0; mi < 4; ++mi) {
        int r0 = bm + warpM + mi * 16 + lq;
        int r1 = r0 + 8;
        float s0 = 1.f, b0 = 0.f, s1 = 1.f, b1 = 0.f;
        if (bn_gamma) {
            float inv0 = bn_gamma[r0] * rsqrtf(bn_var[r0] + 1e-5f);
            float inv1 = bn_gamma[r1] * rsqrtf(bn_var[r1] + 1e-5f);
            s0 = inv0; b0 = bn_beta[r0] - bn_mean[r0] * inv0;
            s1 = inv1; b1 = bn_beta[r1] - bn_mean[r1] * inv1;
        }
#pragma unroll
        for (int ni = 0; ni < 4; ++ni) {
            int n = bn + warpN + ni * 8 + lr * 2;
            float2 v0, v1;
            v0.x = c[mi][ni][0] * s0 + b0;
            v0.y = c[mi][ni][1] * s0 + b0;
            v1.x = c[mi][ni][2] * s1 + b1;
            v1.y = c[mi][ni][3] * s1 + b1;
            *reinterpret_cast<float2*>(&Cp[(size_t)r0 * HW + n]) = v0;
            *reinterpret_cast<float2*>(&Cp[(size_t)r1 * HW + n]) = v1;
        }
    }
}

// ---------------- fused depthwise 5x5 + grouped pointwise 8x8 -> agg ----------------
__global__ __launch_bounds__(256, 2)
void dwpw_kernel(const float* __restrict__ qkv,
                 const float* __restrict__ w_dw,  // [768][25]
                 const float* __restrict__ w_pw,  // [96][8][8]
                 float* __restrict__ agg)
{
    const int tile = blockIdx.x;
    const int g = blockIdx.y;
    const int b = blockIdx.z;
    const int ty0 = (tile >> 1) * 32;
    const int tx0 = (tile & 1) * 32;

    __shared__ float s_in[8][36][36];
    __shared__ float s_dw[8][25];
    __shared__ float s_pw[8][8];

    const int tid = threadIdx.x;
    if (tid < 200) s_dw[tid / 25][tid % 25] = w_dw[(g * 8 + tid / 25) * 25 + tid % 25];
    if (tid < 64)  s_pw[tid >> 3][tid & 7] = w_pw[g * 64 + tid];

    const float* base = qkv + ((size_t)b * 768 + g * 8) * HW;
    for (int idx = tid; idx < 8 * 36 * 36; idx += 256) {
        int c = idx / 1296;
        int rem = idx - c * 1296;
        int r = rem / 36;
        int col = rem - r * 36;
        int y = ty0 + r - 2, x = tx0 + col - 2;
        float v = 0.f;
        if (y >= 0 && y < 64 && x >= 0 && x < 64) v = base[(size_t)c * HW + y * 64 + x];
        s_in[c][r][col] = v;
    }
    __syncthreads();

    float* obase = agg + ((size_t)b * 768 + g * 8) * HW;
#pragma unroll
    for (int pi = 0; pi < 4; ++pi) {
        int p = tid + pi * 256;
        int py = p >> 5, px = p & 31;
        float dwv[8];
#pragma unroll
        for (int c = 0; c < 8; ++c) {
            float a = 0.f;
#pragma unroll
            for (int dy = 0; dy < 5; ++dy)
#pragma unroll
                for (int dx = 0; dx < 5; ++dx)
                    a = fmaf(s_in[c][py + dy][px + dx], s_dw[c][dy * 5 + dx], a);
            dwv[c] = a;
        }
        int off = (ty0 + py) * 64 + (tx0 + px);
#pragma unroll
        for (int o = 0; o < 8; ++o) {
            float a = 0.f;
#pragma unroll
            for (int c = 0; c < 8; ++c) a = fmaf(s_pw[o][c], dwv[c], a);
            obase[(size_t)o * HW + off] = a;
        }
    }
}

// ---------------- kv = sum_p relu(k)_d * [v_e | 1]  per (b, head) ----------------
__global__ __launch_bounds__(256, 4)
void kv_kernel(const float* __restrict__ qkv,
               const float* __restrict__ agg,
               float* __restrict__ kvout)
{
    const int h = blockIdx.x, b = blockIdx.y;
    const float* src = (h < 32) ? qkv : agg;
    const int cbase = (h & 31) * 24;
    const float* kp = src + ((size_t)b * 768 + cbase + 8) * HW;
    const float* vp = src + ((size_t)b * 768 + cbase + 16) * HW;

    float acc[8][9];
#pragma unroll
    for (int d = 0; d < 8; d++)
#pragma unroll
        for (int e = 0; e < 9; e++) acc[d][e] = 0.f;

    for (int p = threadIdx.x; p < HW; p += 256) {
        float kk[8], vv[8];
#pragma unroll
        for (int d = 0; d < 8; d++) kk[d] = fmaxf(kp[(size_t)d * HW + p], 0.f);
#pragma unroll
        for (int e = 0; e < 8; e++) vv[e] = vp[(size_t)e * HW + p];
#pragma unroll
        for (int d = 0; d < 8; d++) {
#pragma unroll
            for (int e = 0; e < 8; e++) acc[d][e] = fmaf(kk[d], vv[e], acc[d][e]);
            acc[d][8] += kk[d];
        }
    }

    __shared__ float red[8][72];
    const int lane = threadIdx.x & 31, w = threadIdx.x >> 5;
#pragma unroll
    for (int i = 0; i < 72; ++i) {
        float v = acc[i / 9][i % 9];
#pragma unroll
        for (int off = 16; off; off >>= 1) v += __shfl_down_sync(0xffffffffu, v, off);
        if (lane == 0) red[w][i] = v;
    }
    __syncthreads();
    if (threadIdx.x < 72) {
        float s = 0.f;
#pragma unroll
        for (int w2 = 0; w2 < 8; ++w2) s += red[w2][threadIdx.x];
        kvout[((size_t)b * 64 + h) * 72 + threadIdx.x] = s;
    }
}

// ---------------- out = (relu(q) @ kv)[:8] / ((relu(q) @ kv)[8] + eps) ----------------
__global__ __launch_bounds__(256, 4)
void apply_kernel(const float* __restrict__ qkv,
                  const float* __restrict__ agg,
                  const float* __restrict__ kvin,
                  float* __restrict__ att)
{
    const int h = blockIdx.y, b = blockIdx.z;
    __shared__ float kv[8][9];
    if (threadIdx.x < 72)
        kv[threadIdx.x / 9][threadIdx.x % 9] = kvin[((size_t)b * 64 + h) * 72 + threadIdx.x];
    __syncthreads();

    const float* src = (h < 32) ? qkv : agg;
    const int cbase = (h & 31) * 24;
    const float* qp = src + ((size_t)b * 768 + cbase) * HW;
    const int p = blockIdx.x * 256 + threadIdx.x;

    float q[8];
#pragma unroll
    for (int d = 0; d < 8; d++) q[d] = fmaxf(qp[(size_t)d * HW + p], 0.f);

    float den = 0.f;
#pragma unroll
    for (int d = 0; d < 8; d++) den = fmaf(q[d], kv[d][8], den);
    const float inv = 1.f / (den + 1e-15f);

    float* op = att + ((size_t)b * 512 + h * 8) * HW + p;
#pragma unroll
    for (int n = 0; n < 8; ++n) {
        float s = 0.f;
#pragma unroll
        for (int d = 0; d < 8; d++) s = fmaf(q[d], kv[d][n], s);
        op[(size_t)n * HW] = s * inv;
    }
}

// ---------------- launch ----------------
extern "C" void kernel_launch(void* const* d_in, const int* in_sizes, int n_in,
                              void* d_out, int out_size)
{
    const float* x        = (const float*)d_in[0];
    const float* w_qkv    = (const float*)d_in[1];
    const float* w_dw     = (const float*)d_in[2];
    const float* w_pw     = (const float*)d_in[3];
    const float* w_proj   = (const float*)d_in[4];
    const float* bn_gamma = (const float*)d_in[5];
    const float* bn_beta  = (const float*)d_in[6];
    const float* bn_mean  = (const float*)d_in[7];
    const float* bn_var   = (const float*)d_in[8];
    float* out = (float*)d_out;

    float *qkv, *agg, *att, *kv;
    cudaGetSymbolAddress((void**)&qkv, g_qkv);
    cudaGetSymbolAddress((void**)&agg, g_agg);
    cudaGetSymbolAddress((void**)&att, g_att);
    cudaGetSymbolAddress((void**)&kv,  g_kv);

    // 1) qkv = w_qkv @ x         (M=768, K=256)
    mma_gemm_kernel<<<dim3(HW / 128, 768 / 128, NB), 256>>>(
        w_qkv, x, qkv, 768, 256, nullptr, nullptr, nullptr, nullptr);

    // 2) agg = grouped-pw(depthwise5x5(qkv))
    dwpw_kernel<<<dim3(4, 96, NB), 256>>>(qkv, w_dw, w_pw, agg);

    // 3) kv reduction per (b, head)
    kv_kernel<<<dim3(64, NB), 256>>>(qkv, agg, kv);

    // 4) normalize / apply -> att [8][512][4096]
    apply_kernel<<<dim3(HW / 256, 64, NB), 256>>>(qkv, agg, kv, att);

    // 5) out = BN(w_proj @ att)  (M=256, K=512)
    mma_gemm_kernel<<<dim3(HW / 128, 256 / 128, NB), 256>>>(
        w_proj, att, out, 256, 512, bn_gamma, bn_beta, bn_mean, bn_var);
}

// round 8
// speedup vs baseline: 1.5718x; 1.4571x over previous
#include <cuda_runtime.h>
#include <cuda_bf16.h>
#include <cstdint>

// ---------------- scratch (no allocations allowed) ----------------
__device__ float g_qkv[(size_t)8 * 768 * 4096];
__device__ float g_agg[(size_t)8 * 768 * 4096];
__device__ float g_att[(size_t)8 * 512 * 4096];
__device__ float g_kv[8 * 64 * 72];

#define HW 4096
#define NB 8

// split (x,y) into packed bf16x2 big + small (residual) parts
__device__ __forceinline__ void split2(float x, float y, uint32_t& big, uint32_t& small) {
    __nv_bfloat162 b = __floats2bfloat162_rn(x, y);
    float bx = __bfloat162float(__low2bfloat16(b));
    float by = __bfloat162float(__high2bfloat16(b));
    __nv_bfloat162 s = __floats2bfloat162_rn(x - bx, y - by);
    big   = *reinterpret_cast<uint32_t*>(&b);
    small = *reinterpret_cast<uint32_t*>(&s);
}

#define MMA_BF16(C, Ar, Br)                                              \
    asm volatile(                                                        \
        "mma.sync.aligned.m16n8k16.row.col.f32.bf16.bf16.f32 "           \
        "{%0,%1,%2,%3}, {%4,%5,%6,%7}, {%8,%9}, {%0,%1,%2,%3};"          \
        : "+f"((C)[0]), "+f"((C)[1]), "+f"((C)[2]), "+f"((C)[3])         \
        : "r"((Ar)[0]), "r"((Ar)[1]), "r"((Ar)[2]), "r"((Ar)[3]),        \
          "r"((Br)[0]), "r"((Br)[1]))

// ---------------- 3-term bf16-split tensor-core GEMM (~fp32 accuracy) ----------------
// C[b](M x 4096) = A(M x K) * B[b](K x 4096), optional fused BN epilogue.
// Block tile 128x128x32, 256 threads = 8 warps (2M x 4N), warp tile 64x32.
// smem holds packed bf16 pairs along K (uint32 = 2 k-values).
__global__ __launch_bounds__(256)
void mma_gemm_kernel(const float* __restrict__ A,     // [M,K] row-major
                     const float* __restrict__ Bsrc,  // [NB][K][4096]
                     float* __restrict__ Cdst,        // [NB][M][4096]
                     int M, int K,
                     const float* __restrict__ bn_gamma,
                     const float* __restrict__ bn_beta,
                     const float* __restrict__ bn_mean,
                     const float* __restrict__ bn_var)
{
    const int b  = blockIdx.z;
    const float* Bp = Bsrc + (size_t)b * K * HW;
    float* Cp       = Cdst + (size_t)b * M * HW;
    const int bm = blockIdx.y * 128;
    const int bn = blockIdx.x * 128;

    // kp = k/2 (packed pairs). K-tile 32 -> 16 kp.
    __shared__ uint32_t As_b[128][20];   // [m][kp], pad 20
    __shared__ uint32_t As_s[128][20];
    __shared__ uint32_t Bs_b[16][136];   // [kp][n], pad 136
    __shared__ uint32_t Bs_s[16][136];

    const int tid  = threadIdx.x;
    const int lane = tid & 31;
    const int warp = tid >> 5;
    const int warpM = (warp >> 2) * 64;   // 0 or 64
    const int warpN = (warp & 3) * 32;    // 0,32,64,96
    const int lq = lane >> 2;             // 0..7
    const int lr = lane & 3;              // 0..3

    float c[4][4][4];
#pragma unroll
    for (int mi = 0; mi < 4; mi++)
#pragma unroll
        for (int ni = 0; ni < 4; ni++)
#pragma unroll
            for (int r = 0; r < 4; r++) c[mi][ni][r] = 0.f;

    for (int k0 = 0; k0 < K; k0 += 32) {
        // ---- A tile: 128 rows x 32 k = 1024 float4 ----
#pragma unroll
        for (int i = 0; i < 4; ++i) {
            int fidx = tid + i * 256;
            int row  = fidx >> 3;
            int kp2  = (fidx & 7) * 2;   // pair index of first pair
            float4 v = *reinterpret_cast<const float4*>(
                &A[(size_t)(bm + row) * K + k0 + kp2 * 2]);
            uint32_t b0, s0, b1, s1;
            split2(v.x, v.y, b0, s0);
            split2(v.z, v.w, b1, s1);
            As_b[row][kp2]     = b0;
            As_b[row][kp2 + 1] = b1;
            As_s[row][kp2]     = s0;
            As_s[row][kp2 + 1] = s1;
        }
        // ---- B tile: 32 k x 128 n; pack (k even, k odd) pairs per n ----
#pragma unroll
        for (int i = 0; i < 2; ++i) {
            int fidx = tid + i * 256;        // 512 tasks: 16 kp x 32 n4
            int kp   = fidx >> 5;
            int n4   = (fidx & 31) * 4;
            const float* r0 = &Bp[(size_t)(k0 + 2 * kp) * HW + bn + n4];
            float4 v0 = *reinterpret_cast<const float4*>(r0);
            float4 v1 = *reinterpret_cast<const float4*>(r0 + HW);
            uint32_t bb0, ss0, bb1, ss1, bb2, ss2, bb3, ss3;
            split2(v0.x, v1.x, bb0, ss0);
            split2(v0.y, v1.y, bb1, ss1);
            split2(v0.z, v1.z, bb2, ss2);
            split2(v0.w, v1.w, bb3, ss3);
            Bs_b[kp][n4 + 0] = bb0; Bs_b[kp][n4 + 1] = bb1;
            Bs_b[kp][n4 + 2] = bb2; Bs_b[kp][n4 + 3] = bb3;
            Bs_s[kp][n4 + 0] = ss0; Bs_s[kp][n4 + 1] = ss1;
            Bs_s[kp][n4 + 2] = ss2; Bs_s[kp][n4 + 3] = ss3;
        }
        __syncthreads();

#pragma unroll
        for (int ks = 0; ks < 2; ++ks) {     // two K=16 steps
            const int kb = ks * 8;           // kp base
            uint32_t ab[4][4], as[4][4], bb[4][2], bs[4][2];
#pragma unroll
            for (int mi = 0; mi < 4; ++mi) {
                int r = warpM + mi * 16 + lq;
                ab[mi][0] = As_b[r][kb + lr];
                ab[mi][1] = As_b[r + 8][kb + lr];
                ab[mi][2] = As_b[r][kb + lr + 4];
                ab[mi][3] = As_b[r + 8][kb + lr + 4];
                as[mi][0] = As_s[r][kb + lr];
                as[mi][1] = As_s[r + 8][kb + lr];
                as[mi][2] = As_s[r][kb + lr + 4];
                as[mi][3] = As_s[r + 8][kb + lr + 4];
            }
#pragma unroll
            for (int ni = 0; ni < 4; ++ni) {
                int col = warpN + ni * 8 + lq;
                bb[ni][0] = Bs_b[kb + lr][col];
                bb[ni][1] = Bs_b[kb + lr + 4][col];
                bs[ni][0] = Bs_s[kb + lr][col];
                bs[ni][1] = Bs_s[kb + lr + 4][col];
            }
#pragma unroll
            for (int mi = 0; mi < 4; ++mi)
#pragma unroll
                for (int ni = 0; ni < 4; ++ni) {
                    MMA_BF16(c[mi][ni], as[mi], bb[ni]);  // small x big
                    MMA_BF16(c[mi][ni], ab[mi], bs[ni]);  // big x small
                    MMA_BF16(c[mi][ni], ab[mi], bb[ni]);  // big x big
                }
        }
        __syncthreads();
    }

    // ---- epilogue: optional BN, float2 stores ----
#pragma unroll
    for (int mi = 0; mi < 4; ++mi) {
        int r0 = bm + warpM + mi * 16 + lq;
        int r1 = r0 + 8;
        float s0 = 1.f, b0 = 0.f, s1 = 1.f, b1 = 0.f;
        if (bn_gamma) {
            float inv0 = bn_gamma[r0] * rsqrtf(bn_var[r0] + 1e-5f);
            float inv1 = bn_gamma[r1] * rsqrtf(bn_var[r1] + 1e-5f);
            s0 = inv0; b0 = bn_beta[r0] - bn_mean[r0] * inv0;
            s1 = inv1; b1 = bn_beta[r1] - bn_mean[r1] * inv1;
        }
#pragma unroll
        for (int ni = 0; ni < 4; ++ni) {
            int n = bn + warpN + ni * 8 + lr * 2;
            float2 v0, v1;
            v0.x = c[mi][ni][0] * s0 + b0;
            v0.y = c[mi][ni][1] * s0 + b0;
            v1.x = c[mi][ni][2] * s1 + b1;
            v1.y = c[mi][ni][3] * s1 + b1;
            *reinterpret_cast<float2*>(&Cp[(size_t)r0 * HW + n]) = v0;
            *reinterpret_cast<float2*>(&Cp[(size_t)r1 * HW + n]) = v1;
        }
    }
}

// ---------------- fused depthwise 5x5 + grouped pointwise 8x8 -> agg ----------------
__global__ __launch_bounds__(256, 2)
void dwpw_kernel(const float* __restrict__ qkv,
                 const float* __restrict__ w_dw,  // [768][25]
                 const float* __restrict__ w_pw,  // [96][8][8]
                 float* __restrict__ agg)
{
    const int tile = blockIdx.x;
    const int g = blockIdx.y;
    const int b = blockIdx.z;
    const int ty0 = (tile >> 1) * 32;
    const int tx0 = (tile & 1) * 32;

    __shared__ float s_in[8][36][36];
    __shared__ float s_dw[8][25];
    __shared__ float s_pw[8][8];

    const int tid = threadIdx.x;
    if (tid < 200) s_dw[tid / 25][tid % 25] = w_dw[(g * 8 + tid / 25) * 25 + tid % 25];
    if (tid < 64)  s_pw[tid >> 3][tid & 7] = w_pw[g * 64 + tid];

    const float* base = qkv + ((size_t)b * 768 + g * 8) * HW;
    for (int idx = tid; idx < 8 * 36 * 36; idx += 256) {
        int c = idx / 1296;
        int rem = idx - c * 1296;
        int r = rem / 36;
        int col = rem - r * 36;
        int y = ty0 + r - 2, x = tx0 + col - 2;
        float v = 0.f;
        if (y >= 0 && y < 64 && x >= 0 && x < 64) v = base[(size_t)c * HW + y * 64 + x];
        s_in[c][r][col] = v;
    }
    __syncthreads();

    float* obase = agg + ((size_t)b * 768 + g * 8) * HW;
#pragma unroll
    for (int pi = 0; pi < 4; ++pi) {
        int p = tid + pi * 256;
        int py = p >> 5, px = p & 31;
        float dwv[8];
#pragma unroll
        for (int c = 0; c < 8; ++c) {
            float a = 0.f;
#pragma unroll
            for (int dy = 0; dy < 5; ++dy)
#pragma unroll
                for (int dx = 0; dx < 5; ++dx)
                    a = fmaf(s_in[c][py + dy][px + dx], s_dw[c][dy * 5 + dx], a);
            dwv[c] = a;
        }
        int off = (ty0 + py) * 64 + (tx0 + px);
#pragma unroll
        for (int o = 0; o < 8; ++o) {
            float a = 0.f;
#pragma unroll
            for (int c = 0; c < 8; ++c) a = fmaf(s_pw[o][c], dwv[c], a);
            obase[(size_t)o * HW + off] = a;
        }
    }
}

// ---------------- kv = sum_p relu(k)_d * [v_e | 1]  per (b, head) ----------------
__global__ __launch_bounds__(256, 4)
void kv_kernel(const float* __restrict__ qkv,
               const float* __restrict__ agg,
               float* __restrict__ kvout)
{
    const int h = blockIdx.x, b = blockIdx.y;
    const float* src = (h < 32) ? qkv : agg;
    const int cbase = (h & 31) * 24;
    const float* kp = src + ((size_t)b * 768 + cbase + 8) * HW;
    const float* vp = src + ((size_t)b * 768 + cbase + 16) * HW;

    float acc[8][9];
#pragma unroll
    for (int d = 0; d < 8; d++)
#pragma unroll
        for (int e = 0; e < 9; e++) acc[d][e] = 0.f;

    for (int p = threadIdx.x; p < HW; p += 256) {
        float kk[8], vv[8];
#pragma unroll
        for (int d = 0; d < 8; d++) kk[d] = fmaxf(kp[(size_t)d * HW + p], 0.f);
#pragma unroll
        for (int e = 0; e < 8; e++) vv[e] = vp[(size_t)e * HW + p];
#pragma unroll
        for (int d = 0; d < 8; d++) {
#pragma unroll
            for (int e = 0; e < 8; e++) acc[d][e] = fmaf(kk[d], vv[e], acc[d][e]);
            acc[d][8] += kk[d];
        }
    }

    __shared__ float red[8][72];
    const int lane = threadIdx.x & 31, w = threadIdx.x >> 5;
#pragma unroll
    for (int i = 0; i < 72; ++i) {
        float v = acc[i / 9][i % 9];
#pragma unroll
        for (int off = 16; off; off >>= 1) v += __shfl_down_sync(0xffffffffu, v, off);
        if (lane == 0) red[w][i] = v;
    }
    __syncthreads();
    if (threadIdx.x < 72) {
        float s = 0.f;
#pragma unroll
        for (int w2 = 0; w2 < 8; ++w2) s += red[w2][threadIdx.x];
        kvout[((size_t)b * 64 + h) * 72 + threadIdx.x] = s;
    }
}

// ---------------- out = (relu(q) @ kv)[:8] / ((relu(q) @ kv)[8] + eps) ----------------
__global__ __launch_bounds__(256, 4)
void apply_kernel(const float* __restrict__ qkv,
                  const float* __restrict__ agg,
                  const float* __restrict__ kvin,
                  float* __restrict__ att)
{
    const int h = blockIdx.y, b = blockIdx.z;
    __shared__ float kv[8][9];
    if (threadIdx.x < 72)
        kv[threadIdx.x / 9][threadIdx.x % 9] = kvin[((size_t)b * 64 + h) * 72 + threadIdx.x];
    __syncthreads();

    const float* src = (h < 32) ? qkv : agg;
    const int cbase = (h & 31) * 24;
    const float* qp = src + ((size_t)b * 768 + cbase) * HW;
    const int p = blockIdx.x * 256 + threadIdx.x;

    float q[8];
#pragma unroll
    for (int d = 0; d < 8; d++) q[d] = fmaxf(qp[(size_t)d * HW + p], 0.f);

    float den = 0.f;
#pragma unroll
    for (int d = 0; d < 8; d++) den = fmaf(q[d], kv[d][8], den);
    const float inv = 1.f / (den + 1e-15f);

    float* op = att + ((size_t)b * 512 + h * 8) * HW + p;
#pragma unroll
    for (int n = 0; n < 8; ++n) {
        float s = 0.f;
#pragma unroll
        for (int d = 0; d < 8; d++) s = fmaf(q[d], kv[d][n], s);
        op[(size_t)n * HW] = s * inv;
    }
}

// ---------------- launch ----------------
extern "C" void kernel_launch(void* const* d_in, const int* in_sizes, int n_in,
                              void* d_out, int out_size)
{
    const float* x        = (const float*)d_in[0];
    const float* w_qkv    = (const float*)d_in[1];
    const float* w_dw     = (const float*)d_in[2];
    const float* w_pw     = (const float*)d_in[3];
    const float* w_proj   = (const float*)d_in[4];
    const float* bn_gamma = (const float*)d_in[5];
    const float* bn_beta  = (const float*)d_in[6];
    const float* bn_mean  = (const float*)d_in[7];
    const float* bn_var   = (const float*)d_in[8];
    float* out = (float*)d_out;

    float *qkv, *agg, *att, *kv;
    cudaGetSymbolAddress((void**)&qkv, g_qkv);
    cudaGetSymbolAddress((void**)&agg, g_agg);
    cudaGetSymbolAddress((void**)&att, g_att);
    cudaGetSymbolAddress((void**)&kv,  g_kv);

    // 1) qkv = w_qkv @ x         (M=768, K=256)
    mma_gemm_kernel<<<dim3(HW / 128, 768 / 128, NB), 256>>>(
        w_qkv, x, qkv, 768, 256, nullptr, nullptr, nullptr, nullptr);

    // 2) agg = grouped-pw(depthwise5x5(qkv))
    dwpw_kernel<<<dim3(4, 96, NB), 256>>>(qkv, w_dw, w_pw, agg);

    // 3) kv reduction per (b, head)
    kv_kernel<<<dim3(64, NB), 256>>>(qkv, agg, kv);

    // 4) normalize / apply -> att [8][512][4096]
    apply_kernel<<<dim3(HW / 256, 64, NB), 256>>>(qkv, agg, kv, att);

    // 5) out = BN(w_proj @ att)  (M=256, K=512)
    mma_gemm_kernel<<<dim3(HW / 128, 256 / 128, NB), 256>>>(
        w_proj, att, out, 256, 512, bn_gamma, bn_beta, bn_mean, bn_var);
}

// round 10
// speedup vs baseline: 1.5893x; 1.0112x over previous
#include <cuda_runtime.h>
#include <cuda_fp16.h>
#include <cstdint>

// ---------------- scratch (no allocations allowed) ----------------
__device__ float    g_qkv[(size_t)8 * 768 * 4096];   // fp32
__device__ float    g_agg[(size_t)8 * 768 * 4096];   // fp32
__device__ float    g_kv[8 * 64 * 72];
// packed half2 (k even, k odd) split operands
__device__ uint32_t g_xb[(size_t)8 * 128 * 4096];    // x big   [b][kp][px]
__device__ uint32_t g_xs[(size_t)8 * 128 * 4096];    // x small
__device__ uint32_t g_attb[(size_t)8 * 256 * 4096];  // att big [b][kp][px]
__device__ uint32_t g_atts[(size_t)8 * 256 * 4096];
__device__ uint32_t g_wqb[768 * 128];                // w_qkv big  [m][kp]
__device__ uint32_t g_wqs[768 * 128];
__device__ uint32_t g_wpb[256 * 256];                // w_proj big [m][kp]
__device__ uint32_t g_wps[256 * 256];

#define HW 4096
#define NB 8
#define A_SCALE 128.0f
#define B_SCALE 16.0f
#define INV_SC  (1.0f / (A_SCALE * B_SCALE))   // 2^-11

// split scaled pair into packed fp16 big + small
__device__ __forceinline__ void splith(float x, float y, float sc,
                                       uint32_t& pb, uint32_t& ps) {
    float xs = x * sc, ys = y * sc;
    __half hx = __float2half_rn(xs), hy = __float2half_rn(ys);
    float rx = xs - __half2float(hx), ry = ys - __half2float(hy);
    __half sx = __float2half_rn(rx), sy = __float2half_rn(ry);
    __half2 vb = __halves2half2(hx, hy);
    __half2 vs = __halves2half2(sx, sy);
    pb = *reinterpret_cast<uint32_t*>(&vb);
    ps = *reinterpret_cast<uint32_t*>(&vs);
}

#define MMA_F16(C, Ar, Br)                                               \
    asm volatile(                                                        \
        "mma.sync.aligned.m16n8k16.row.col.f32.f16.f16.f32 "             \
        "{%0,%1,%2,%3}, {%4,%5,%6,%7}, {%8,%9}, {%0,%1,%2,%3};"          \
        : "+f"((C)[0]), "+f"((C)[1]), "+f"((C)[2]), "+f"((C)[3])         \
        : "r"((Ar)[0]), "r"((Ar)[1]), "r"((Ar)[2]), "r"((Ar)[3]),        \
          "r"((Br)[0]), "r"((Br)[1]))

#define CP_ASYNC16(smem_addr, gptr)                                      \
    asm volatile("cp.async.cg.shared.global [%0], [%1], 16;"             \
                 :: "r"(smem_addr), "l"(gptr) : "memory")

// ---------------- weight split kernel (tiny) ----------------
__global__ void split_w_kernel(const float* __restrict__ wq,
                               const float* __restrict__ wp)
{
    int idx = blockIdx.x * 256 + threadIdx.x;
    if (idx < 768 * 128) {
        int m = idx >> 7, kp = idx & 127;
        float2 v = *reinterpret_cast<const float2*>(&wq[m * 256 + 2 * kp]);
        splith(v.x, v.y, A_SCALE, g_wqb[idx], g_wqs[idx]);
    } else {
        int j = idx - 768 * 128;
        if (j < 256 * 256) {
            int m = j >> 8, kp = j & 255;
            float2 v = *reinterpret_cast<const float2*>(&wp[m * 512 + 2 * kp]);
            splith(v.x, v.y, A_SCALE, g_wpb[j], g_wps[j]);
        }
    }
}

// ---------------- x split kernel ----------------
__global__ __launch_bounds__(256)
void split_x_kernel(const float* __restrict__ x)
{
    int idx = blockIdx.x * 256 + threadIdx.x;    // [b][kp][p]
    int p = idx & 4095;
    int rest = idx >> 12;
    int kp = rest & 127;
    int b = rest >> 7;
    const float* xp = x + ((size_t)b * 256 + 2 * kp) * HW + p;
    splith(xp[0], xp[HW], B_SCALE, g_xb[idx], g_xs[idx]);
}

// ---------------- fp16 split tensor-core GEMM, cp.async double-buffered ----------------
// C[b](M x 4096) = (A * B) * INV_SC  (+BN). A pre-split [M][Kp] u32, B pre-split [NB][Kp][4096] u32.
// Block tile 128x128, chunk 16 kp (K=32). 256 threads, 8 warps (2M x 4N), warp tile 64x32.
// stage layout (bytes): Ab[128][20] 10240 | As 10240 | Bb[16][136] 8704 | Bs 8704 = 37888
#define ST_AS 10240
#define ST_BB 20480
#define ST_BS 29184
#define STAGE 37888
#define GEMM_SMEM (2 * STAGE)   // 75776

__global__ __launch_bounds__(256, 2)
void gemm_kernel(const uint32_t* __restrict__ Ab, const uint32_t* __restrict__ As,
                 const uint32_t* __restrict__ Bb, const uint32_t* __restrict__ Bs,
                 float* __restrict__ Cdst, int Kp,
                 const float* __restrict__ bn_gamma, const float* __restrict__ bn_beta,
                 const float* __restrict__ bn_mean,  const float* __restrict__ bn_var)
{
    extern __shared__ __align__(16) char smem[];
    uint32_t sbase;
    asm("{ .reg .u64 t; cvta.to.shared.u64 t, %1; cvt.u32.u64 %0, t; }"
        : "=r"(sbase) : "l"(smem));

    const int tid  = threadIdx.x;
    const int lane = tid & 31;
    const int warp = tid >> 5;
    const int warpM = (warp >> 2) * 64;
    const int warpN = (warp & 3) * 32;
    const int lq = lane >> 2;
    const int lr = lane & 3;

    const int b  = blockIdx.z;
    const int m0 = blockIdx.y * 128;
    const int n0 = blockIdx.x * 128;
    const int M  = gridDim.y * 128;
    const uint32_t* Bpb = Bb + (size_t)b * Kp * HW;
    const uint32_t* Bps = Bs + (size_t)b * Kp * HW;
    float* Cp = Cdst + (size_t)b * M * HW;

    // per-thread cp.async source/dest precompute
    const int arow = tid >> 2, aq = (tid & 3) * 4;          // A: 2 tasks (tid, tid+256)
    const int arow2 = (tid + 256) >> 2, aq2 = ((tid + 256) & 3) * 4;
    const int brow = tid >> 5, bcg = (tid & 31) * 4;        // B: 2 tasks
    const int brow2 = (tid + 256) >> 5, bcg2 = ((tid + 256) & 31) * 4;

    float c[4][4][4];
#pragma unroll
    for (int mi = 0; mi < 4; mi++)
#pragma unroll
        for (int ni = 0; ni < 4; ni++)
#pragma unroll
            for (int r = 0; r < 4; r++) c[mi][ni][r] = 0.f;

    const int nch = Kp >> 4;

    auto load_stage = [&](int st, int ck) {
        uint32_t sb = sbase + st * STAGE;
        const uint32_t* a0 = Ab + (size_t)(m0 + arow) * Kp + ck * 16 + aq;
        const uint32_t* a1 = Ab + (size_t)(m0 + arow2) * Kp + ck * 16 + aq2;
        const uint32_t* a2 = As + (size_t)(m0 + arow) * Kp + ck * 16 + aq;
        const uint32_t* a3 = As + (size_t)(m0 + arow2) * Kp + ck * 16 + aq2;
        CP_ASYNC16(sb + (arow * 20 + aq) * 4, a0);
        CP_ASYNC16(sb + (arow2 * 20 + aq2) * 4, a1);
        CP_ASYNC16(sb + ST_AS + (arow * 20 + aq) * 4, a2);
        CP_ASYNC16(sb + ST_AS + (arow2 * 20 + aq2) * 4, a3);
        const uint32_t* b0 = Bpb + (size_t)(ck * 16 + brow) * HW + n0 + bcg;
        const uint32_t* b1 = Bpb + (size_t)(ck * 16 + brow2) * HW + n0 + bcg2;
        const uint32_t* b2 = Bps + (size_t)(ck * 16 + brow) * HW + n0 + bcg;
        const uint32_t* b3 = Bps + (size_t)(ck * 16 + brow2) * HW + n0 + bcg2;
        CP_ASYNC16(sb + ST_BB + (brow * 136 + bcg) * 4, b0);
        CP_ASYNC16(sb + ST_BB + (brow2 * 136 + bcg2) * 4, b1);
        CP_ASYNC16(sb + ST_BS + (brow * 136 + bcg) * 4, b2);
        CP_ASYNC16(sb + ST_BS + (brow2 * 136 + bcg2) * 4, b3);
        asm volatile("cp.async.commit_group;" ::: "memory");
    };

    load_stage(0, 0);

    for (int ck = 0; ck < nch; ++ck) {
        if (ck + 1 < nch) {
            load_stage((ck + 1) & 1, ck + 1);
            asm volatile("cp.async.wait_group 1;" ::: "memory");
        } else {
            asm volatile("cp.async.wait_group 0;" ::: "memory");
        }
        __syncthreads();

        const uint32_t* Ab_s = (const uint32_t*)(smem + (ck & 1) * STAGE);
        const uint32_t* As_s = (const uint32_t*)(smem + (ck & 1) * STAGE + ST_AS);
        const uint32_t* Bb_s = (const uint32_t*)(smem + (ck & 1) * STAGE + ST_BB);
        const uint32_t* Bs_s = (const uint32_t*)(smem + (ck & 1) * STAGE + ST_BS);

#pragma unroll
        for (int ks = 0; ks < 2; ++ks) {
            const int kb = ks * 8;
            uint32_t bbf[4][2], bsf[4][2];
#pragma unroll
            for (int ni = 0; ni < 4; ++ni) {
                int col = warpN + ni * 8 + lq;
                bbf[ni][0] = Bb_s[(kb + lr) * 136 + col];
                bbf[ni][1] = Bb_s[(kb + lr + 4) * 136 + col];
                bsf[ni][0] = Bs_s[(kb + lr) * 136 + col];
                bsf[ni][1] = Bs_s[(kb + lr + 4) * 136 + col];
            }
#pragma unroll
            for (int mi = 0; mi < 4; ++mi) {
                int r = warpM + mi * 16 + lq;
                int kc = kb + lr;
                uint32_t abf[4] = { Ab_s[r * 20 + kc], Ab_s[(r + 8) * 20 + kc],
                                    Ab_s[r * 20 + kc + 4], Ab_s[(r + 8) * 20 + kc + 4] };
                uint32_t asf[4] = { As_s[r * 20 + kc], As_s[(r + 8) * 20 + kc],
                                    As_s[r * 20 + kc + 4], As_s[(r + 8) * 20 + kc + 4] };
#pragma unroll
                for (int ni = 0; ni < 4; ++ni) {
                    MMA_F16(c[mi][ni], asf, bbf[ni]);   // small x big
                    MMA_F16(c[mi][ni], abf, bsf[ni]);   // big x small
                    MMA_F16(c[mi][ni], abf, bbf[ni]);   // big x big
                }
            }
        }
        __syncthreads();
    }

    // ---- epilogue: descale + optional BN ----
#pragma unroll
    for (int mi = 0; mi < 4; ++mi) {
        int r0 = m0 + warpM + mi * 16 + lq;
        int r1 = r0 + 8;
        float s0 = INV_SC, b0 = 0.f, s1 = INV_SC, b1 = 0.f;
        if (bn_gamma) {
            float inv0 = bn_gamma[r0] * rsqrtf(bn_var[r0] + 1e-5f);
            float inv1 = bn_gamma[r1] * rsqrtf(bn_var[r1] + 1e-5f);
            s0 = inv0 * INV_SC; b0 = bn_beta[r0] - bn_mean[r0] * inv0;
            s1 = inv1 * INV_SC; b1 = bn_beta[r1] - bn_mean[r1] * inv1;
        }
#pragma unroll
        for (int ni = 0; ni < 4; ++ni) {
            int n = n0 + warpN + ni * 8 + lr * 2;
            float2 v0, v1;
            v0.x = c[mi][ni][0] * s0 + b0;
            v0.y = c[mi][ni][1] * s0 + b0;
            v1.x = c[mi][ni][2] * s1 + b1;
            v1.y = c[mi][ni][3] * s1 + b1;
            *reinterpret_cast<float2*>(&Cp[(size_t)r0 * HW + n]) = v0;
            *reinterpret_cast<float2*>(&Cp[(size_t)r1 * HW + n]) = v1;
        }
    }
}

// ---------------- fused depthwise 5x5 + grouped pointwise 8x8 -> agg ----------------
__global__ __launch_bounds__(256, 2)
void dwpw_kernel(const float* __restrict__ qkv,
                 const float* __restrict__ w_dw,
                 const float* __restrict__ w_pw,
                 float* __restrict__ agg)
{
    const int tile = blockIdx.x;
    const int g = blockIdx.y;
    const int b = blockIdx.z;
    const int ty0 = (tile >> 1) * 32;
    const int tx0 = (tile & 1) * 32;

    __shared__ float s_in[8][36][36];
    __shared__ float s_dw[8][25];
    __shared__ float s_pw[8][8];

    const int tid = threadIdx.x;
    if (tid < 200) s_dw[tid / 25][tid % 25] = w_dw[(g * 8 + tid / 25) * 25 + tid % 25];
    if (tid < 64)  s_pw[tid >> 3][tid & 7] = w_pw[g * 64 + tid];

    const float* base = qkv + ((size_t)b * 768 + g * 8) * HW;
    for (int idx = tid; idx < 8 * 36 * 36; idx += 256) {
        int c = idx / 1296;
        int rem = idx - c * 1296;
        int r = rem / 36;
        int col = rem - r * 36;
        int y = ty0 + r - 2, x = tx0 + col - 2;
        float v = 0.f;
        if (y >= 0 && y < 64 && x >= 0 && x < 64) v = base[(size_t)c * HW + y * 64 + x];
        s_in[c][r][col] = v;
    }
    __syncthreads();

    float* obase = agg + ((size_t)b * 768 + g * 8) * HW;
#pragma unroll
    for (int pi = 0; pi < 4; ++pi) {
        int p = tid + pi * 256;
        int py = p >> 5, px = p & 31;
        float dwv[8];
#pragma unroll
        for (int c = 0; c < 8; ++c) {
            float a = 0.f;
#pragma unroll
            for (int dy = 0; dy < 5; ++dy)
#pragma unroll
                for (int dx = 0; dx < 5; ++dx)
                    a = fmaf(s_in[c][py + dy][px + dx], s_dw[c][dy * 5 + dx], a);
            dwv[c] = a;
        }
        int off = (ty0 + py) * 64 + (tx0 + px);
#pragma unroll
        for (int o = 0; o < 8; ++o) {
            float a = 0.f;
#pragma unroll
            for (int c = 0; c < 8; ++c) a = fmaf(s_pw[o][c], dwv[c], a);
            obase[(size_t)o * HW + off] = a;
        }
    }
}

// ---------------- kv = sum_p relu(k)_d * [v_e | 1]  per (b, head) ----------------
__global__ __launch_bounds__(256, 4)
void kv_kernel(const float* __restrict__ qkv,
               const float* __restrict__ agg,
               float* __restrict__ kvout)
{
    const int h = blockIdx.x, b = blockIdx.y;
    const float* src = (h < 32) ? qkv : agg;
    const int cbase = (h & 31) * 24;
    const float* kp = src + ((size_t)b * 768 + cbase + 8) * HW;
    const float* vp = src + ((size_t)b * 768 + cbase + 16) * HW;

    float acc[8][9];
#pragma unroll
    for (int d = 0; d < 8; d++)
#pragma unroll
        for (int e = 0; e < 9; e++) acc[d][e] = 0.f;

    for (int p = threadIdx.x; p < HW; p += 256) {
        float kk[8], vv[8];
#pragma unroll
        for (int d = 0; d < 8; d++) kk[d] = fmaxf(kp[(size_t)d * HW + p], 0.f);
#pragma unroll
        for (int e = 0; e < 8; e++) vv[e] = vp[(size_t)e * HW + p];
#pragma unroll
        for (int d = 0; d < 8; d++) {
#pragma unroll
            for (int e = 0; e < 8; e++) acc[d][e] = fmaf(kk[d], vv[e], acc[d][e]);
            acc[d][8] += kk[d];
        }
    }

    __shared__ float red[8][72];
    const int lane = threadIdx.x & 31, w = threadIdx.x >> 5;
#pragma unroll
    for (int i = 0; i < 72; ++i) {
        float v = acc[i / 9][i % 9];
#pragma unroll
        for (int off = 16; off; off >>= 1) v += __shfl_down_sync(0xffffffffu, v, off);
        if (lane == 0) red[w][i] = v;
    }
    __syncthreads();
    if (threadIdx.x < 72) {
        float s = 0.f;
#pragma unroll
        for (int w2 = 0; w2 < 8; ++w2) s += red[w2][threadIdx.x];
        kvout[((size_t)b * 64 + h) * 72 + threadIdx.x] = s;
    }
}

// ---------------- apply + fused att split: out=(relu(q)@kv)[:8]/(den+eps) -> fp16 split ----------------
__global__ __launch_bounds__(256, 4)
void apply_kernel(const float* __restrict__ qkv,
                  const float* __restrict__ agg,
                  const float* __restrict__ kvin,
                  uint32_t* __restrict__ attb,
                  uint32_t* __restrict__ atts)
{
    const int h = blockIdx.y, b = blockIdx.z;
    __shared__ float kv[8][9];
    if (threadIdx.x < 72)
        kv[threadIdx.x / 9][threadIdx.x % 9] = kvin[((size_t)b * 64 + h) * 72 + threadIdx.x];
    __syncthreads();

    const float* src = (h < 32) ? qkv : agg;
    const int cbase = (h & 31) * 24;
    const float* qp = src + ((size_t)b * 768 + cbase) * HW;
    const int p = blockIdx.x * 256 + threadIdx.x;

    float q[8];
#pragma unroll
    for (int d = 0; d < 8; d++) q[d] = fmaxf(qp[(size_t)d * HW + p], 0.f);

    float den = 0.f;
#pragma unroll
    for (int d = 0; d < 8; d++) den = fmaf(q[d], kv[d][8], den);
    const float inv = 1.f / (den + 1e-15f);

    float o[8];
#pragma unroll
    for (int n = 0; n < 8; ++n) {
        float s = 0.f;
#pragma unroll
        for (int d = 0; d < 8; d++) s = fmaf(q[d], kv[d][n], s);
        o[n] = s * inv;
    }

    uint32_t* wb = attb + ((size_t)b * 256 + h * 4) * HW + p;
    uint32_t* ws = atts + ((size_t)b * 256 + h * 4) * HW + p;
#pragma unroll
    for (int j = 0; j < 4; ++j) {
        uint32_t ub, us;
        splith(o[2 * j], o[2 * j + 1], B_SCALE, ub, us);
        wb[(size_t)j * HW] = ub;
        ws[(size_t)j * HW] = us;
    }
}

// ---------------- launch ----------------
extern "C" void kernel_launch(void* const* d_in, const int* in_sizes, int n_in,
                              void* d_out, int out_size)
{
    const float* x        = (const float*)d_in[0];
    const float* w_qkv    = (const float*)d_in[1];
    const float* w_dw     = (const float*)d_in[2];
    const float* w_pw     = (const float*)d_in[3];
    const float* w_proj   = (const float*)d_in[4];
    const float* bn_gamma = (const float*)d_in[5];
    const float* bn_beta  = (const float*)d_in[6];
    const float* bn_mean  = (const float*)d_in[7];
    const float* bn_var   = (const float*)d_in[8];
    float* out = (float*)d_out;

    float *qkv, *agg, *kv;
    uint32_t *xb, *xs, *attb, *atts, *wqb, *wqs, *wpb, *wps;
    cudaGetSymbolAddress((void**)&qkv,  g_qkv);
    cudaGetSymbolAddress((void**)&agg,  g_agg);
    cudaGetSymbolAddress((void**)&kv,   g_kv);
    cudaGetSymbolAddress((void**)&xb,   g_xb);
    cudaGetSymbolAddress((void**)&xs,   g_xs);
    cudaGetSymbolAddress((void**)&attb, g_attb);
    cudaGetSymbolAddress((void**)&atts, g_atts);
    cudaGetSymbolAddress((void**)&wqb,  g_wqb);
    cudaGetSymbolAddress((void**)&wqs,  g_wqs);
    cudaGetSymbolAddress((void**)&wpb,  g_wpb);
    cudaGetSymbolAddress((void**)&wps,  g_wps);

    cudaFuncSetAttribute(gemm_kernel,
                         cudaFuncAttributeMaxDynamicSharedMemorySize, GEMM_SMEM);

    // 0) pre-split weights and x into fp16 big/small (packed pairs)
    split_w_kernel<<<(768 * 128 + 256 * 256 + 255) / 256, 256>>>(w_qkv, w_proj);
    split_x_kernel<<<(8 * 128 * 4096) / 256, 256>>>(x);

    // 1) qkv = w_qkv @ x   (M=768, Kp=128)
    gemm_kernel<<<dim3(HW / 128, 6, NB), 256, GEMM_SMEM>>>(
        wqb, wqs, xb, xs, qkv, 128, nullptr, nullptr, nullptr, nullptr);

    // 2) agg = grouped-pw(depthwise5x5(qkv))
    dwpw_kernel<<<dim3(4, 96, NB), 256>>>(qkv, w_dw, w_pw, agg);

    // 3) kv reduction per (b, head)
    kv_kernel<<<dim3(64, NB), 256>>>(qkv, agg, kv);

    // 4) apply -> att (fp16 split, fused)
    apply_kernel<<<dim3(HW / 256, 64, NB), 256>>>(qkv, agg, kv, attb, atts);

    // 5) out = BN(w_proj @ att)   (M=256, Kp=256)
    gemm_kernel<<<dim3(HW / 128, 2, NB), 256, GEMM_SMEM>>>(
        wpb, wps, attb, atts, out, 256, bn_gamma, bn_beta, bn_mean, bn_var);
}

// round 11
// speedup vs baseline: 2.0899x; 1.3150x over previous
#include <cuda_runtime.h>
#include <cuda_fp16.h>
#include <cstdint>

// ---------------- scratch (no allocations allowed) ----------------
__device__ float    g_qkv[(size_t)8 * 768 * 4096];   // fp32
__device__ float    g_agg[(size_t)8 * 768 * 4096];   // fp32
__device__ float    g_kv[8 * 64 * 72];
// packed half2 (k even, k odd) split operands
__device__ uint32_t g_xb[(size_t)8 * 128 * 4096];    // x big   [b][kp][px]
__device__ uint32_t g_xs[(size_t)8 * 128 * 4096];    // x small
__device__ uint32_t g_attb[(size_t)8 * 256 * 4096];  // att big [b][kp][px]
__device__ uint32_t g_atts[(size_t)8 * 256 * 4096];
__device__ uint32_t g_wqb[768 * 128];                // w_qkv big  [m][kp]
__device__ uint32_t g_wqs[768 * 128];
__device__ uint32_t g_wpb[256 * 256];                // w_proj big [m][kp]
__device__ uint32_t g_wps[256 * 256];

#define HW 4096
#define NB 8
#define A_SCALE 128.0f
#define B_SCALE 16.0f
#define INV_SC  (1.0f / (A_SCALE * B_SCALE))   // 2^-11

// split scaled pair into packed fp16 big + small
__device__ __forceinline__ void splith(float x, float y, float sc,
                                       uint32_t& pb, uint32_t& ps) {
    float xs = x * sc, ys = y * sc;
    __half hx = __float2half_rn(xs), hy = __float2half_rn(ys);
    float rx = xs - __half2float(hx), ry = ys - __half2float(hy);
    __half sx = __float2half_rn(rx), sy = __float2half_rn(ry);
    __half2 vb = __halves2half2(hx, hy);
    __half2 vs = __halves2half2(sx, sy);
    pb = *reinterpret_cast<uint32_t*>(&vb);
    ps = *reinterpret_cast<uint32_t*>(&vs);
}

#define MMA_F16(C, Ar, Br)                                               \
    asm volatile(                                                        \
        "mma.sync.aligned.m16n8k16.row.col.f32.f16.f16.f32 "             \
        "{%0,%1,%2,%3}, {%4,%5,%6,%7}, {%8,%9}, {%0,%1,%2,%3};"          \
        : "+f"((C)[0]), "+f"((C)[1]), "+f"((C)[2]), "+f"((C)[3])         \
        : "r"((Ar)[0]), "r"((Ar)[1]), "r"((Ar)[2]), "r"((Ar)[3]),        \
          "r"((Br)[0]), "r"((Br)[1]))

#define CP_ASYNC16(smem_addr, gptr)                                      \
    asm volatile("cp.async.cg.shared.global [%0], [%1], 16;"             \
                 :: "r"(smem_addr), "l"(gptr) : "memory")

// ---------------- weight split kernel (tiny) ----------------
__global__ void split_w_kernel(const float* __restrict__ wq,
                               const float* __restrict__ wp)
{
    int idx = blockIdx.x * 256 + threadIdx.x;
    if (idx < 768 * 128) {
        int m = idx >> 7, kp = idx & 127;
        float2 v = *reinterpret_cast<const float2*>(&wq[m * 256 + 2 * kp]);
        splith(v.x, v.y, A_SCALE, g_wqb[idx], g_wqs[idx]);
    } else {
        int j = idx - 768 * 128;
        if (j < 256 * 256) {
            int m = j >> 8, kp = j & 255;
            float2 v = *reinterpret_cast<const float2*>(&wp[m * 512 + 2 * kp]);
            splith(v.x, v.y, A_SCALE, g_wpb[j], g_wps[j]);
        }
    }
}

// ---------------- x split kernel ----------------
__global__ __launch_bounds__(256)
void split_x_kernel(const float* __restrict__ x)
{
    int idx = blockIdx.x * 256 + threadIdx.x;    // [b][kp][p]
    int p = idx & 4095;
    int rest = idx >> 12;
    int kp = rest & 127;
    int b = rest >> 7;
    const float* xp = x + ((size_t)b * 256 + 2 * kp) * HW + p;
    splith(xp[0], xp[HW], B_SCALE, g_xb[idx], g_xs[idx]);
}

// ---------------- fp16 split tensor-core GEMM, cp.async double-buffered ----------------
#define ST_AS 10240
#define ST_BB 20480
#define ST_BS 29184
#define STAGE 37888
#define GEMM_SMEM (2 * STAGE)   // 75776

__global__ __launch_bounds__(256, 2)
void gemm_kernel(const uint32_t* __restrict__ Ab, const uint32_t* __restrict__ As,
                 const uint32_t* __restrict__ Bb, const uint32_t* __restrict__ Bs,
                 float* __restrict__ Cdst, int Kp,
                 const float* __restrict__ bn_gamma, const float* __restrict__ bn_beta,
                 const float* __restrict__ bn_mean,  const float* __restrict__ bn_var)
{
    extern __shared__ __align__(16) char smem[];
    uint32_t sbase;
    asm("{ .reg .u64 t; cvta.to.shared.u64 t, %1; cvt.u32.u64 %0, t; }"
        : "=r"(sbase) : "l"(smem));

    const int tid  = threadIdx.x;
    const int lane = tid & 31;
    const int warp = tid >> 5;
    const int warpM = (warp >> 2) * 64;
    const int warpN = (warp & 3) * 32;
    const int lq = lane >> 2;
    const int lr = lane & 3;

    const int b  = blockIdx.z;
    const int m0 = blockIdx.y * 128;
    const int n0 = blockIdx.x * 128;
    const int M  = gridDim.y * 128;
    const uint32_t* Bpb = Bb + (size_t)b * Kp * HW;
    const uint32_t* Bps = Bs + (size_t)b * Kp * HW;
    float* Cp = Cdst + (size_t)b * M * HW;

    const int arow = tid >> 2, aq = (tid & 3) * 4;
    const int arow2 = (tid + 256) >> 2, aq2 = ((tid + 256) & 3) * 4;
    const int brow = tid >> 5, bcg = (tid & 31) * 4;
    const int brow2 = (tid + 256) >> 5, bcg2 = ((tid + 256) & 31) * 4;

    float c[4][4][4];
#pragma unroll
    for (int mi = 0; mi < 4; mi++)
#pragma unroll
        for (int ni = 0; ni < 4; ni++)
#pragma unroll
            for (int r = 0; r < 4; r++) c[mi][ni][r] = 0.f;

    const int nch = Kp >> 4;

    auto load_stage = [&](int st, int ck) {
        uint32_t sb = sbase + st * STAGE;
        const uint32_t* a0 = Ab + (size_t)(m0 + arow) * Kp + ck * 16 + aq;
        const uint32_t* a1 = Ab + (size_t)(m0 + arow2) * Kp + ck * 16 + aq2;
        const uint32_t* a2 = As + (size_t)(m0 + arow) * Kp + ck * 16 + aq;
        const uint32_t* a3 = As + (size_t)(m0 + arow2) * Kp + ck * 16 + aq2;
        CP_ASYNC16(sb + (arow * 20 + aq) * 4, a0);
        CP_ASYNC16(sb + (arow2 * 20 + aq2) * 4, a1);
        CP_ASYNC16(sb + ST_AS + (arow * 20 + aq) * 4, a2);
        CP_ASYNC16(sb + ST_AS + (arow2 * 20 + aq2) * 4, a3);
        const uint32_t* b0 = Bpb + (size_t)(ck * 16 + brow) * HW + n0 + bcg;
        const uint32_t* b1 = Bpb + (size_t)(ck * 16 + brow2) * HW + n0 + bcg2;
        const uint32_t* b2 = Bps + (size_t)(ck * 16 + brow) * HW + n0 + bcg;
        const uint32_t* b3 = Bps + (size_t)(ck * 16 + brow2) * HW + n0 + bcg2;
        CP_ASYNC16(sb + ST_BB + (brow * 136 + bcg) * 4, b0);
        CP_ASYNC16(sb + ST_BB + (brow2 * 136 + bcg2) * 4, b1);
        CP_ASYNC16(sb + ST_BS + (brow * 136 + bcg) * 4, b2);
        CP_ASYNC16(sb + ST_BS + (brow2 * 136 + bcg2) * 4, b3);
        asm volatile("cp.async.commit_group;" ::: "memory");
    };

    load_stage(0, 0);

    for (int ck = 0; ck < nch; ++ck) {
        if (ck + 1 < nch) {
            load_stage((ck + 1) & 1, ck + 1);
            asm volatile("cp.async.wait_group 1;" ::: "memory");
        } else {
            asm volatile("cp.async.wait_group 0;" ::: "memory");
        }
        __syncthreads();

        const uint32_t* Ab_s = (const uint32_t*)(smem + (ck & 1) * STAGE);
        const uint32_t* As_s = (const uint32_t*)(smem + (ck & 1) * STAGE + ST_AS);
        const uint32_t* Bb_s = (const uint32_t*)(smem + (ck & 1) * STAGE + ST_BB);
        const uint32_t* Bs_s = (const uint32_t*)(smem + (ck & 1) * STAGE + ST_BS);

#pragma unroll
        for (int ks = 0; ks < 2; ++ks) {
            const int kb = ks * 8;
            uint32_t bbf[4][2], bsf[4][2];
#pragma unroll
            for (int ni = 0; ni < 4; ++ni) {
                int col = warpN + ni * 8 + lq;
                bbf[ni][0] = Bb_s[(kb + lr) * 136 + col];
                bbf[ni][1] = Bb_s[(kb + lr + 4) * 136 + col];
                bsf[ni][0] = Bs_s[(kb + lr) * 136 + col];
                bsf[ni][1] = Bs_s[(kb + lr + 4) * 136 + col];
            }
#pragma unroll
            for (int mi = 0; mi < 4; ++mi) {
                int r = warpM + mi * 16 + lq;
                int kc = kb + lr;
                uint32_t abf[4] = { Ab_s[r * 20 + kc], Ab_s[(r + 8) * 20 + kc],
                                    Ab_s[r * 20 + kc + 4], Ab_s[(r + 8) * 20 + kc + 4] };
                uint32_t asf[4] = { As_s[r * 20 + kc], As_s[(r + 8) * 20 + kc],
                                    As_s[r * 20 + kc + 4], As_s[(r + 8) * 20 + kc + 4] };
#pragma unroll
                for (int ni = 0; ni < 4; ++ni) {
                    MMA_F16(c[mi][ni], asf, bbf[ni]);   // small x big
                    MMA_F16(c[mi][ni], abf, bsf[ni]);   // big x small
                    MMA_F16(c[mi][ni], abf, bbf[ni]);   // big x big
                }
            }
        }
        __syncthreads();
    }

#pragma unroll
    for (int mi = 0; mi < 4; ++mi) {
        int r0 = m0 + warpM + mi * 16 + lq;
        int r1 = r0 + 8;
        float s0 = INV_SC, b0 = 0.f, s1 = INV_SC, b1 = 0.f;
        if (bn_gamma) {
            float inv0 = bn_gamma[r0] * rsqrtf(bn_var[r0] + 1e-5f);
            float inv1 = bn_gamma[r1] * rsqrtf(bn_var[r1] + 1e-5f);
            s0 = inv0 * INV_SC; b0 = bn_beta[r0] - bn_mean[r0] * inv0;
            s1 = inv1 * INV_SC; b1 = bn_beta[r1] - bn_mean[r1] * inv1;
        }
#pragma unroll
        for (int ni = 0; ni < 4; ++ni) {
            int n = n0 + warpN + ni * 8 + lr * 2;
            float2 v0, v1;
            v0.x = c[mi][ni][0] * s0 + b0;
            v0.y = c[mi][ni][1] * s0 + b0;
            v1.x = c[mi][ni][2] * s1 + b1;
            v1.y = c[mi][ni][3] * s1 + b1;
            *reinterpret_cast<float2*>(&Cp[(size_t)r0 * HW + n]) = v0;
            *reinterpret_cast<float2*>(&Cp[(size_t)r1 * HW + n]) = v1;
        }
    }
}

// ---------------- fused depthwise 5x5 + grouped pointwise 8x8 -> agg ----------------
// Register-blocked: each thread computes a 4-row x 1-col strip (px = lane-consecutive).
// Per channel: 25 weights preloaded to regs; 8 input rows x 5-wide window -> 4 accumulators.
__global__ __launch_bounds__(256, 2)
void dwpw_kernel(const float* __restrict__ qkv,
                 const float* __restrict__ w_dw,
                 const float* __restrict__ w_pw,
                 float* __restrict__ agg)
{
    const int tile = blockIdx.x;
    const int g = blockIdx.y;
    const int b = blockIdx.z;
    const int ty0 = (tile >> 1) * 32;
    const int tx0 = (tile & 1) * 32;

    __shared__ float s_in[8][36][36];
    __shared__ float s_dw[8][25];
    __shared__ float s_pw[8][8];

    const int tid = threadIdx.x;
    if (tid < 200) s_dw[tid / 25][tid % 25] = w_dw[(g * 8 + tid / 25) * 25 + tid % 25];
    if (tid < 64)  s_pw[tid >> 3][tid & 7] = w_pw[g * 64 + tid];

    const float* base = qkv + ((size_t)b * 768 + g * 8) * HW;
    for (int idx = tid; idx < 8 * 36 * 36; idx += 256) {
        int c = idx / 1296;
        int rem = idx - c * 1296;
        int r = rem / 36;
        int col = rem - r * 36;
        int y = ty0 + r - 2, x = tx0 + col - 2;
        float v = 0.f;
        if (y >= 0 && y < 64 && x >= 0 && x < 64) v = base[(size_t)c * HW + y * 64 + x];
        s_in[c][r][col] = v;
    }
    __syncthreads();

    const int px  = tid & 31;       // column within tile
    const int py0 = (tid >> 5) * 4; // strip of 4 output rows

    float out[8][4];
#pragma unroll
    for (int o = 0; o < 8; ++o)
#pragma unroll
        for (int p = 0; p < 4; ++p) out[o][p] = 0.f;

#pragma unroll
    for (int c = 0; c < 8; ++c) {
        float w[25];
#pragma unroll
        for (int i = 0; i < 25; ++i) w[i] = s_dw[c][i];

        float acc[4] = {0.f, 0.f, 0.f, 0.f};
#pragma unroll
        for (int j = 0; j < 8; ++j) {       // input rows py0-2 .. py0+5 (smem rows py0+j)
            float win[5];
#pragma unroll
            for (int dx = 0; dx < 5; ++dx) win[dx] = s_in[c][py0 + j][px + dx];
#pragma unroll
            for (int o = 0; o < 4; ++o) {
                const int dy = j - o;       // compile-time per (j,o)
                if (dy >= 0 && dy <= 4) {
#pragma unroll
                    for (int dx = 0; dx < 5; ++dx)
                        acc[o] = fmaf(win[dx], w[dy * 5 + dx], acc[o]);
                }
            }
        }
#pragma unroll
        for (int o = 0; o < 8; ++o) {
            float pw = s_pw[o][c];
#pragma unroll
            for (int p = 0; p < 4; ++p) out[o][p] = fmaf(pw, acc[p], out[o][p]);
        }
    }

    float* obase = agg + ((size_t)b * 768 + g * 8) * HW;
#pragma unroll
    for (int o = 0; o < 8; ++o) {
#pragma unroll
        for (int p = 0; p < 4; ++p) {
            int off = (ty0 + py0 + p) * 64 + (tx0 + px);
            obase[(size_t)o * HW + off] = out[o][p];
        }
    }
}

// ---------------- kv = sum_p relu(k)_d * [v_e | 1]  per (b, head) ----------------
__global__ __launch_bounds__(256, 4)
void kv_kernel(const float* __restrict__ qkv,
               const float* __restrict__ agg,
               float* __restrict__ kvout)
{
    const int h = blockIdx.x, b = blockIdx.y;
    const float* src = (h < 32) ? qkv : agg;
    const int cbase = (h & 31) * 24;
    const float* kp = src + ((size_t)b * 768 + cbase + 8) * HW;
    const float* vp = src + ((size_t)b * 768 + cbase + 16) * HW;

    float acc[8][9];
#pragma unroll
    for (int d = 0; d < 8; d++)
#pragma unroll
        for (int e = 0; e < 9; e++) acc[d][e] = 0.f;

    for (int p = threadIdx.x; p < HW; p += 256) {
        float kk[8], vv[8];
#pragma unroll
        for (int d = 0; d < 8; d++) kk[d] = fmaxf(kp[(size_t)d * HW + p], 0.f);
#pragma unroll
        for (int e = 0; e < 8; e++) vv[e] = vp[(size_t)e * HW + p];
#pragma unroll
        for (int d = 0; d < 8; d++) {
#pragma unroll
            for (int e = 0; e < 8; e++) acc[d][e] = fmaf(kk[d], vv[e], acc[d][e]);
            acc[d][8] += kk[d];
        }
    }

    __shared__ float red[8][72];
    const int lane = threadIdx.x & 31, w = threadIdx.x >> 5;
#pragma unroll
    for (int i = 0; i < 72; ++i) {
        float v = acc[i / 9][i % 9];
#pragma unroll
        for (int off = 16; off; off >>= 1) v += __shfl_down_sync(0xffffffffu, v, off);
        if (lane == 0) red[w][i] = v;
    }
    __syncthreads();
    if (threadIdx.x < 72) {
        float s = 0.f;
#pragma unroll
        for (int w2 = 0; w2 < 8; ++w2) s += red[w2][threadIdx.x];
        kvout[((size_t)b * 64 + h) * 72 + threadIdx.x] = s;
    }
}

// ---------------- apply + fused att split ----------------
__global__ __launch_bounds__(256, 4)
void apply_kernel(const float* __restrict__ qkv,
                  const float* __restrict__ agg,
                  const float* __restrict__ kvin,
                  uint32_t* __restrict__ attb,
                  uint32_t* __restrict__ atts)
{
    const int h = blockIdx.y, b = blockIdx.z;
    __shared__ float kv[8][9];
    if (threadIdx.x < 72)
        kv[threadIdx.x / 9][threadIdx.x % 9] = kvin[((size_t)b * 64 + h) * 72 + threadIdx.x];
    __syncthreads();

    const float* src = (h < 32) ? qkv : agg;
    const int cbase = (h & 31) * 24;
    const float* qp = src + ((size_t)b * 768 + cbase) * HW;
    const int p = blockIdx.x * 256 + threadIdx.x;

    float q[8];
#pragma unroll
    for (int d = 0; d < 8; d++) q[d] = fmaxf(qp[(size_t)d * HW + p], 0.f);

    float den = 0.f;
#pragma unroll
    for (int d = 0; d < 8; d++) den = fmaf(q[d], kv[d][8], den);
    const float inv = 1.f / (den + 1e-15f);

    float o[8];
#pragma unroll
    for (int n = 0; n < 8; ++n) {
        float s = 0.f;
#pragma unroll
        for (int d = 0; d < 8; d++) s = fmaf(q[d], kv[d][n], s);
        o[n] = s * inv;
    }

    uint32_t* wb = attb + ((size_t)b * 256 + h * 4) * HW + p;
    uint32_t* ws = atts + ((size_t)b * 256 + h * 4) * HW + p;
#pragma unroll
    for (int j = 0; j < 4; ++j) {
        uint32_t ub, us;
        splith(o[2 * j], o[2 * j + 1], B_SCALE, ub, us);
        wb[(size_t)j * HW] = ub;
        ws[(size_t)j * HW] = us;
    }
}

// ---------------- launch ----------------
extern "C" void kernel_launch(void* const* d_in, const int* in_sizes, int n_in,
                              void* d_out, int out_size)
{
    const float* x        = (const float*)d_in[0];
    const float* w_qkv    = (const float*)d_in[1];
    const float* w_dw     = (const float*)d_in[2];
    const float* w_pw     = (const float*)d_in[3];
    const float* w_proj   = (const float*)d_in[4];
    const float* bn_gamma = (const float*)d_in[5];
    const float* bn_beta  = (const float*)d_in[6];
    const float* bn_mean  = (const float*)d_in[7];
    const float* bn_var   = (const float*)d_in[8];
    float* out = (float*)d_out;

    float *qkv, *agg, *kv;
    uint32_t *xb, *xs, *attb, *atts, *wqb, *wqs, *wpb, *wps;
    cudaGetSymbolAddress((void**)&qkv,  g_qkv);
    cudaGetSymbolAddress((void**)&agg,  g_agg);
    cudaGetSymbolAddress((void**)&kv,   g_kv);
    cudaGetSymbolAddress((void**)&xb,   g_xb);
    cudaGetSymbolAddress((void**)&xs,   g_xs);
    cudaGetSymbolAddress((void**)&attb, g_attb);
    cudaGetSymbolAddress((void**)&atts, g_atts);
    cudaGetSymbolAddress((void**)&wqb,  g_wqb);
    cudaGetSymbolAddress((void**)&wqs,  g_wqs);
    cudaGetSymbolAddress((void**)&wpb,  g_wpb);
    cudaGetSymbolAddress((void**)&wps,  g_wps);

    cudaFuncSetAttribute(gemm_kernel,
                         cudaFuncAttributeMaxDynamicSharedMemorySize, GEMM_SMEM);

    // 0) pre-split weights and x into fp16 big/small (packed pairs)
    split_w_kernel<<<(768 * 128 + 256 * 256 + 255) / 256, 256>>>(w_qkv, w_proj);
    split_x_kernel<<<(8 * 128 * 4096) / 256, 256>>>(x);

    // 1) qkv = w_qkv @ x   (M=768, Kp=128)
    gemm_kernel<<<dim3(HW / 128, 6, NB), 256, GEMM_SMEM>>>(
        wqb, wqs, xb, xs, qkv, 128, nullptr, nullptr, nullptr, nullptr);

    // 2) agg = grouped-pw(depthwise5x5(qkv))
    dwpw_kernel<<<dim3(4, 96, NB), 256>>>(qkv, w_dw, w_pw, agg);

    // 3) kv reduction per (b, head)
    kv_kernel<<<dim3(64, NB), 256>>>(qkv, agg, kv);

    // 4) apply -> att (fp16 split, fused)
    apply_kernel<<<dim3(HW / 256, 64, NB), 256>>>(qkv, agg, kv, attb, atts);

    // 5) out = BN(w_proj @ att)   (M=256, Kp=256)
    gemm_kernel<<<dim3(HW / 128, 2, NB), 256, GEMM_SMEM>>>(
        wpb, wps, attb, atts, out, 256, bn_gamma, bn_beta, bn_mean, bn_var);
}